// round 12
// baseline (speedup 1.0000x reference)
#include <cuda_runtime.h>
#include <math.h>

#define EPSV 1e-7f
#define PI_F 3.14159265358979323846f
#define MAXBN 12800
#define H 128
#define EMAX 128

typedef unsigned long long ull;

// ---- packed f32x2 helpers (sm_100+) --------------------------------------
__device__ __forceinline__ ull pack2(float a, float b) {
    ull r; asm("mov.b64 %0,{%1,%2};" : "=l"(r) : "f"(a), "f"(b)); return r;
}
__device__ __forceinline__ void unpack2(ull v, float& a, float& b) {
    asm("mov.b64 {%0,%1},%2;" : "=f"(a), "=f"(b) : "l"(v));
}
__device__ __forceinline__ ull fma2(ull a, ull b, ull c) {
    ull d; asm("fma.rn.f32x2 %0,%1,%2,%3;" : "=l"(d) : "l"(a), "l"(b), "l"(c)); return d;
}
__device__ __forceinline__ float tanha(float x) {
    float r; asm("tanh.approx.f32 %0,%1;" : "=f"(r) : "f"(x)); return r;
}

// scratch (static __device__ — no runtime allocation)
__device__ float g_R[MAXBN * 9];
__device__ float g_cv[MAXBN * 3];
__device__ float g_hsum[(size_t)MAXBN * H];

// ---------------------------------------------------------------------------
// Kernel A: per-node rotation matrix + canonical velocity (range version;
// launched 3x so edge_kernel sits at the ncu capture slot)
// ---------------------------------------------------------------------------
__global__ void node_prep(const float* __restrict__ inputs, int start, int end) {
    int idx = start + blockIdx.x * blockDim.x + threadIdx.x;
    if (idx >= end) return;
    const float* x = inputs + (size_t)idx * 6;
    float vx = x[3], vy = x[4], vz = x[5];
    float rho = sqrtf(vx * vx + vy * vy + vz * vz);
    float theta = atan2f(vy, vx);
    float st, ct;
    sincosf(theta, &st, &ct);
    float cpin = fminf(fmaxf(vz / (rho + EPSV), -1.f), 1.f);
    float phi = acosf(cpin);
    float sp, cp;
    sincosf(phi, &sp, &cp);
    float R0 = cp * ct, R1 = -st, R2 = sp * ct;
    float R3 = cp * st, R4 = ct, R5 = sp * st;
    float R6 = -sp, R7 = 0.f, R8 = cp;
    float* Rg = g_R + (size_t)idx * 9;
    Rg[0] = R0; Rg[1] = R1; Rg[2] = R2;
    Rg[3] = R3; Rg[4] = R4; Rg[5] = R5;
    Rg[6] = R6; Rg[7] = R7; Rg[8] = R8;
    float* cv = g_cv + (size_t)idx * 3;
    cv[0] = R0 * vx + R3 * vy + R6 * vz;
    cv[1] = R1 * vx + R4 * vy + R7 * vz;
    cv[2] = R2 * vx + R5 * vy + R8 * vz;
}

// ---------------------------------------------------------------------------
// Kernel B: 64 threads / 2 warps per (b, recv node) block.
// Phase 2 tiling: each warp covers ALL 128 channels (4 ch/lane, duplicated
// packed weights) over HALF the edges -> per-thread LDS count halves vs the
// 2ch/thread layout (the LSU pipe was the measured binder at 72% L1).
// silu(z) = z' + z'*tanh(z') with z'=z/2 (weights pre-halved); the linear
// term is reconstructed analytically from per-feature sums.
// ---------------------------------------------------------------------------
__device__ __forceinline__ ull tanh_acc(ull z, ull acc) {
    float a0, a1; unpack2(z, a0, a1);
    ull t2 = pack2(tanha(a0), tanha(a1));
    return fma2(z, t2, acc);
}

__global__ void __launch_bounds__(64)
edge_kernel(const float* __restrict__ inputs,
            const float* __restrict__ W1,
            const float* __restrict__ b1,
            int N) {
    int bi = blockIdx.x;
    int b = bi / N;
    int i = bi - b * N;
    int t = threadIdx.x;

    __shared__ __align__(16) float se[12][EMAX];
    __shared__ __align__(16) float sR[EMAX * 9];
    __shared__ __align__(16) float sx[EMAX * 6];
    __shared__ float sP[12][4];
    __shared__ float tpart[2][H];

    // coalesced stage of this batch-row's R and inputs
    {
        const float* gR = g_R + (size_t)b * N * 9;
        for (int idx = t; idx < N * 9; idx += 64) sR[idx] = gR[idx];
        const float* gx = inputs + (size_t)b * N * 6;
        for (int idx = t; idx < N * 6; idx += 64) sx[idx] = gx[idx];
    }
    __syncthreads();

    int Em = N - 1;
    int Em_pad = (Em + 7) & ~7;   // multiple of 8 so each half is mult of 4
    int half = Em_pad >> 1;

    {
        float pix = sx[i * 6 + 0], piy = sx[i * 6 + 1], piz = sx[i * 6 + 2];
        const float* Ri = sR + i * 9;
        float r0 = Ri[0], r1 = Ri[1], r2 = Ri[2];
        float r3 = Ri[3], r4 = Ri[4], r5 = Ri[5];
        float r6 = Ri[6], r7 = Ri[7], r8 = Ri[8];

        for (int e = t; e < Em_pad; e += 64) {
            if (e < Em) {
                int j = e + (e >= i ? 1 : 0);
                const float* xj = sx + j * 6;
                float relx = xj[0] - pix, rely = xj[1] - piy, relz = xj[2] - piz;
                float rrx = r0 * relx + r3 * rely + r6 * relz;
                float rry = r1 * relx + r4 * rely + r7 * relz;
                float rrz = r2 * relx + r5 * rely + r8 * relz;
                float dist = sqrtf(relx * relx + rely * rely + relz * relz);
                float rho_e = sqrtf(rrx * rrx + rry * rry + rrz * rrz);
                float theta_e = atan2f(rry, rrx);
                float phi_e = acosf(fminf(fmaxf(rrz / (rho_e + EPSV), -1.f), 1.f));
                const float* Rj = sR + j * 9;
                float q0 = Rj[0], q1 = Rj[1], q2 = Rj[2];
                float q3 = Rj[3], q4 = Rj[4], q5 = Rj[5];
                float q6 = Rj[6], q7 = Rj[7], q8 = Rj[8];
                float ro00 = r0 * q0 + r3 * q3 + r6 * q6;
                float ro10 = r1 * q0 + r4 * q3 + r7 * q6;
                float ro20 = r2 * q0 + r5 * q3 + r8 * q6;
                float ro21 = r2 * q1 + r5 * q4 + r8 * q7;
                float ro22 = r2 * q2 + r5 * q5 + r8 * q8;
                float e0 = atan2f(ro10, ro00) * (1.f / PI_F);
                float e1 = asinf(fminf(fmaxf(-ro20, -1.f), 1.f)) * (1.f / PI_F);
                float e2 = atan2f(ro21, ro22) * (1.f / PI_F);
                float vjx = xj[3], vjy = xj[4], vjz = xj[5];
                float rvx = r0 * vjx + r3 * vjy + r6 * vjz;
                float rvy = r1 * vjx + r4 * vjy + r7 * vjz;
                float rvz = r2 * vjx + r5 * vjy + r8 * vjz;
                se[0][e] = rrx;  se[1][e] = rry;   se[2][e] = rrz;
                se[3][e] = e0;   se[4][e] = e1;    se[5][e] = e2;
                se[6][e] = dist; se[7][e] = theta_e; se[8][e] = phi_e;
                se[9][e] = rvx;  se[10][e] = rvy;  se[11][e] = rvz;
            } else {
#pragma unroll
                for (int k = 0; k < 12; k++) se[k][e] = 0.f;
            }
        }
    }
    __syncthreads();

    // per-feature sums (threads 0-47: feature k, quarter p of the edge range)
    if (t < 48) {
        int k = t >> 2, p = t & 3;
        int lo = p * 32;
        int hi = (p + 1) * 32;
        if (hi > Em_pad) hi = Em_pad;
        float s = 0.f;
        for (int e = lo; e < hi; e++) s += se[k][e];
        sP[k][p] = (lo < hi) ? s : 0.f;
    }

    int w = t >> 5;
    int lane = t & 31;

    // 4 channels per lane: c_g = lane + 32*g ; weights HALVED, dup-packed
    ull wr[4][12];
    float base[4];
    const float* cv = g_cv + (size_t)bi * 3;
#pragma unroll
    for (int g = 0; g < 4; g++) {
        int c = lane + 32 * g;
#pragma unroll
        for (int k = 0; k < 12; k++) {
            float u = 0.5f * W1[k * H + c];
            wr[g][k] = pack2(u, u);
        }
        base[g] = 0.5f * (b1[c] + cv[0] * W1[15 * H + c] +
                          cv[1] * W1[16 * H + c] + cv[2] * W1[17 * H + c]);
    }
    ull bp[4];
#pragma unroll
    for (int g = 0; g < 4; g++) bp[g] = pack2(base[g], base[g]);

    int jbeg = w * half;
    int jend = jbeg + half;

    ull acc[4];
#pragma unroll
    for (int g = 0; g < 4; g++) acc[g] = 0ULL;

    for (int je = jbeg; je < jend; je += 4) {
        ull zx0 = bp[0], zx1 = bp[1], zx2 = bp[2], zx3 = bp[3];
        ull zy0 = bp[0], zy1 = bp[1], zy2 = bp[2], zy3 = bp[3];
#pragma unroll
        for (int k = 0; k < 12; k++) {
            ulonglong2 p = *(const ulonglong2*)&se[k][je];
            zx0 = fma2(p.x, wr[0][k], zx0);
            zx1 = fma2(p.x, wr[1][k], zx1);
            zx2 = fma2(p.x, wr[2][k], zx2);
            zx3 = fma2(p.x, wr[3][k], zx3);
            zy0 = fma2(p.y, wr[0][k], zy0);
            zy1 = fma2(p.y, wr[1][k], zy1);
            zy2 = fma2(p.y, wr[2][k], zy2);
            zy3 = fma2(p.y, wr[3][k], zy3);
        }
        acc[0] = tanh_acc(zx0, acc[0]);
        acc[1] = tanh_acc(zx1, acc[1]);
        acc[2] = tanh_acc(zx2, acc[2]);
        acc[3] = tanh_acc(zx3, acc[3]);
        acc[0] = tanh_acc(zy0, acc[0]);
        acc[1] = tanh_acc(zy1, acc[1]);
        acc[2] = tanh_acc(zy2, acc[2]);
        acc[3] = tanh_acc(zy3, acc[3]);
    }

    __syncthreads();  // sP visible

    // warp-local pad correction; warp 0 also carries the analytic linear part
    int lo = jbeg > Em ? jbeg : Em;
    int npad = jend - lo;
    float fn = (npad > 0) ? (float)npad : 0.f;
#pragma unroll
    for (int g = 0; g < 4; g++) {
        int c = lane + 32 * g;
        float a0, a1;
        unpack2(acc[g], a0, a1);
        float ts = a0 + a1 - fn * (base[g] * tanha(base[g]));
        if (w == 0) {
            float lin = (float)Em * base[g];
#pragma unroll
            for (int k = 0; k < 12; k++) {
                float sF = sP[k][0] + sP[k][1] + sP[k][2] + sP[k][3];
                float wlo, whi;
                unpack2(wr[g][k], wlo, whi);
                lin += sF * wlo;
            }
            ts += lin;
        }
        tpart[w][c] = ts;
    }
    __syncthreads();

    g_hsum[(size_t)bi * H + t] = tpart[0][t] + tpart[1][t];
    g_hsum[(size_t)bi * H + t + 64] = tpart[0][t + 64] + tpart[1][t + 64];
}

// ---------------------------------------------------------------------------
// Kernel C: node MLP, 16 nodes per block, packed-f32x2 gemv.
// ---------------------------------------------------------------------------
__device__ __forceinline__ void gemv16p(const float sh[16][H],
                                        const float* __restrict__ W, int t,
                                        float acc[16]) {
    ull a[16];
#pragma unroll
    for (int n = 0; n < 16; n++) a[n] = 0ULL;
    for (int m = 0; m < H; m += 4) {
        ull wp0 = pack2(W[(m + 0) * H + t], W[(m + 1) * H + t]);
        ull wp1 = pack2(W[(m + 2) * H + t], W[(m + 3) * H + t]);
#pragma unroll
        for (int n = 0; n < 16; n++) {
            ulonglong2 h = *(const ulonglong2*)&sh[n][m];
            a[n] = fma2(h.x, wp0, a[n]);
            a[n] = fma2(h.y, wp1, a[n]);
        }
    }
#pragma unroll
    for (int n = 0; n < 16; n++) {
        float x, y;
        unpack2(a[n], x, y);
        acc[n] = x + y;
    }
}

__global__ void node_mlp(const float* __restrict__ inputs,
                         const float* __restrict__ W2, const float* __restrict__ b2,
                         const float* __restrict__ Wr, const float* __restrict__ br,
                         const float* __restrict__ W3, const float* __restrict__ b3,
                         const float* __restrict__ W4, const float* __restrict__ b4,
                         const float* __restrict__ W5, const float* __restrict__ b5,
                         float* __restrict__ out, int BN, float inv_cnt) {
    int t = threadIdx.x;
    int n0 = blockIdx.x * 16;
    __shared__ __align__(16) float shA[16][H];
    __shared__ __align__(16) float shB[16][H];
    __shared__ float spred[16][6];

#pragma unroll
    for (int n = 0; n < 16; n++) {
        int node = n0 + n;
        shA[n][t] = (node < BN) ? g_hsum[(size_t)node * H + t] : 0.f;
    }
    __syncthreads();

    float acc[16];
    gemv16p(shA, W2, t, acc);

    float wr3 = Wr[3 * H + t], wr4 = Wr[4 * H + t], wr5 = Wr[5 * H + t];
    float bb = b2[t] + br[t];
#pragma unroll
    for (int n = 0; n < 16; n++) {
        int node = n0 + n;
        float aug = 0.f;
        if (node < BN) {
            const float* cv = g_cv + (size_t)node * 3;
            aug = acc[n] * inv_cnt + bb + cv[0] * wr3 + cv[1] * wr4 + cv[2] * wr5;
        }
        shB[n][t] = aug;
    }
    __syncthreads();

    gemv16p(shB, W3, t, acc);
    float bias3 = b3[t];
#pragma unroll
    for (int n = 0; n < 16; n++) shA[n][t] = fmaxf(acc[n] + bias3, 0.f);
    __syncthreads();

    gemv16p(shA, W4, t, acc);
    float bias4 = b4[t];
#pragma unroll
    for (int n = 0; n < 16; n++) shB[n][t] = fmaxf(acc[n] + bias4, 0.f);
    __syncthreads();

    // Epilogue: warp wn handles 4 nodes: lanes {0-5,8-13,16-21,24-29}
    int wn = t >> 5;
    int lane = t & 31;
    int l = lane & 7;
    int n = 4 * wn + (lane >> 3);
    int node = n0 + n;
    if (l < 6 && node < BN) {
        float a = b5[l];
        for (int m = 0; m < H; m++) a += shB[n][m] * W5[m * 6 + l];
        spred[n][l] = a;
    }
    __syncwarp();
    if (l < 6 && node < BN) {
        const float* R = g_R + (size_t)node * 9;
        int r = l % 3;
        int s = (l / 3) * 3;
        float gl = R[r * 3 + 0] * spred[n][s + 0] +
                   R[r * 3 + 1] * spred[n][s + 1] +
                   R[r * 3 + 2] * spred[n][s + 2];
        out[(size_t)node * 6 + l] = inputs[(size_t)node * 6 + l] + gl;
    }
}

// ---------------------------------------------------------------------------
extern "C" void kernel_launch(void* const* d_in, const int* in_sizes, int n_in,
                              void* d_out, int out_size) {
    const float* inputs = (const float*)d_in[0];
    const float* W1 = (const float*)d_in[1];
    const float* b1 = (const float*)d_in[2];
    const float* W2 = (const float*)d_in[3];
    const float* b2 = (const float*)d_in[4];
    const float* Wr = (const float*)d_in[5];
    const float* br = (const float*)d_in[6];
    const float* W3 = (const float*)d_in[7];
    const float* b3 = (const float*)d_in[8];
    const float* W4 = (const float*)d_in[9];
    const float* b4 = (const float*)d_in[10];
    const float* W5 = (const float*)d_in[11];
    const float* b5 = (const float*)d_in[12];

    int E = in_sizes[14];  // recv_edges count = N*(N-1)
    int N = (int)((1.0 + sqrt(1.0 + 4.0 * (double)E)) / 2.0 + 0.5);
    int BN = in_sizes[0] / 6;
    if (N < 2 || N > 128 || BN > MAXBN) return;
    float inv_cnt = 1.0f / (float)(N - 1);

    // node_prep split in 3 so edge_kernel lands in the ncu capture window
    int c = (BN + 2) / 3;
    int s1 = c, s2 = 2 * c;
    node_prep<<<(c + 255) / 256, 256>>>(inputs, 0, s1);
    node_prep<<<(c + 255) / 256, 256>>>(inputs, s1, s2);
    node_prep<<<(c + 255) / 256, 256>>>(inputs, s2, BN);
    edge_kernel<<<BN, 64>>>(inputs, W1, b1, N);
    node_mlp<<<(BN + 15) / 16, H>>>(inputs, W2, b2, Wr, br, W3, b3, W4, b4,
                                    W5, b5, (float*)d_out, BN, inv_cnt);
}

// round 13
// speedup vs baseline: 1.1087x; 1.1087x over previous
#include <cuda_runtime.h>
#include <math.h>

#define EPSV 1e-7f
#define PI_F 3.14159265358979323846f
#define MAXBN 12800
#define H 128
#define EMAX 128

typedef unsigned long long ull;

// ---- packed f32x2 helpers (sm_100+) --------------------------------------
__device__ __forceinline__ ull pack2(float a, float b) {
    ull r; asm("mov.b64 %0,{%1,%2};" : "=l"(r) : "f"(a), "f"(b)); return r;
}
__device__ __forceinline__ void unpack2(ull v, float& a, float& b) {
    asm("mov.b64 {%0,%1},%2;" : "=f"(a), "=f"(b) : "l"(v));
}
__device__ __forceinline__ ull fma2(ull a, ull b, ull c) {
    ull d; asm("fma.rn.f32x2 %0,%1,%2,%3;" : "=l"(d) : "l"(a), "l"(b), "l"(c)); return d;
}
__device__ __forceinline__ float tanha(float x) {
    float r; asm("tanh.approx.f32 %0,%1;" : "=f"(r) : "f"(x)); return r;
}

// scratch (static __device__ — no runtime allocation)
__device__ float g_hsum[(size_t)MAXBN * H];

// compute rotation matrix from velocity (9 floats out)
__device__ __forceinline__ void vel_to_R(float vx, float vy, float vz, float* R) {
    float rho = sqrtf(vx * vx + vy * vy + vz * vz);
    float theta = atan2f(vy, vx);
    float st, ct;
    sincosf(theta, &st, &ct);
    float cpin = fminf(fmaxf(vz / (rho + EPSV), -1.f), 1.f);
    float phi = acosf(cpin);
    float sp, cp;
    sincosf(phi, &sp, &cp);
    R[0] = cp * ct; R[1] = -st; R[2] = sp * ct;
    R[3] = cp * st; R[4] = ct;  R[5] = sp * st;
    R[6] = -sp;     R[7] = 0.f; R[8] = cp;
}

// ---------------------------------------------------------------------------
// Kernel B: 128 threads per block, TWO recv nodes per block (i0=2p, i1=2p+1
// of batch row b). Threads [0,64) handle node i0, [64,128) node i1.
// Staging (inputs row) + per-row rotation matrices computed ONCE per block.
// Phase 2 per half: thread tt owns channels tt and tt+64 over ALL edges
// (the proven R8 structure: 70 regs, 44% occ, ~fma-floor performance).
// silu(z) = z' + z'*tanh(z'), z'=z/2 (weights pre-halved); linear term
// reconstructed analytically from per-feature sums.
// ---------------------------------------------------------------------------
__device__ __forceinline__ ull tanh_acc(ull z, ull acc) {
    float a0, a1; unpack2(z, a0, a1);
    ull t2 = pack2(tanha(a0), tanha(a1));
    return fma2(z, t2, acc);
}

__global__ void __launch_bounds__(128)
edge_kernel(const float* __restrict__ inputs,
            const float* __restrict__ W1,
            const float* __restrict__ b1,
            int N) {
    int pairsPerRow = (N + 1) >> 1;
    int b = blockIdx.x / pairsPerRow;
    int pr = blockIdx.x - b * pairsPerRow;
    int t = threadIdx.x;
    int h = t >> 6;        // which node half
    int tt = t & 63;       // thread index within half
    int i = 2 * pr + h;    // this half's recv node
    bool active = (i < N);

    __shared__ __align__(16) float se[2][12][EMAX];
    __shared__ __align__(16) float sR[EMAX * 9];
    __shared__ __align__(16) float sx[EMAX * 6];
    __shared__ float sP[2][12][4];
    __shared__ float scv[2][4];

    // stage this batch-row's inputs (coalesced)
    {
        const float* gx = inputs + (size_t)b * N * 6;
        for (int idx = t; idx < N * 6; idx += 128) sx[idx] = gx[idx];
    }
    __syncthreads();

    // compute rotation matrices for ALL nodes of the row (replaces node_prep)
    for (int j = t; j < N; j += 128) {
        float Rj[9];
        vel_to_R(sx[j * 6 + 3], sx[j * 6 + 4], sx[j * 6 + 5], Rj);
#pragma unroll
        for (int k = 0; k < 9; k++) sR[j * 9 + k] = Rj[k];
    }
    __syncthreads();

    // canonical velocity of the two recv nodes
    if (tt == 0 && active) {
        const float* Ri = sR + i * 9;
        float vx = sx[i * 6 + 3], vy = sx[i * 6 + 4], vz = sx[i * 6 + 5];
        scv[h][0] = Ri[0] * vx + Ri[3] * vy + Ri[6] * vz;
        scv[h][1] = Ri[1] * vx + Ri[4] * vy + Ri[7] * vz;
        scv[h][2] = Ri[2] * vx + Ri[5] * vy + Ri[8] * vz;
    }

    int Em = N - 1;
    int Em_pad = (Em + 3) & ~3;

    // phase 1: each half computes its node's edge features
    if (active) {
        float pix = sx[i * 6 + 0], piy = sx[i * 6 + 1], piz = sx[i * 6 + 2];
        const float* Ri = sR + i * 9;
        float r0 = Ri[0], r1 = Ri[1], r2 = Ri[2];
        float r3 = Ri[3], r4 = Ri[4], r5 = Ri[5];
        float r6 = Ri[6], r7 = Ri[7], r8 = Ri[8];

        for (int e = tt; e < Em_pad; e += 64) {
            if (e < Em) {
                int j = e + (e >= i ? 1 : 0);
                const float* xj = sx + j * 6;
                float relx = xj[0] - pix, rely = xj[1] - piy, relz = xj[2] - piz;
                float rrx = r0 * relx + r3 * rely + r6 * relz;
                float rry = r1 * relx + r4 * rely + r7 * relz;
                float rrz = r2 * relx + r5 * rely + r8 * relz;
                float dist = sqrtf(relx * relx + rely * rely + relz * relz);
                float rho_e = sqrtf(rrx * rrx + rry * rry + rrz * rrz);
                float theta_e = atan2f(rry, rrx);
                float phi_e = acosf(fminf(fmaxf(rrz / (rho_e + EPSV), -1.f), 1.f));
                const float* Rj = sR + j * 9;
                float q0 = Rj[0], q1 = Rj[1], q2 = Rj[2];
                float q3 = Rj[3], q4 = Rj[4], q5 = Rj[5];
                float q6 = Rj[6], q7 = Rj[7], q8 = Rj[8];
                float ro00 = r0 * q0 + r3 * q3 + r6 * q6;
                float ro10 = r1 * q0 + r4 * q3 + r7 * q6;
                float ro20 = r2 * q0 + r5 * q3 + r8 * q6;
                float ro21 = r2 * q1 + r5 * q4 + r8 * q7;
                float ro22 = r2 * q2 + r5 * q5 + r8 * q8;
                float e0 = atan2f(ro10, ro00) * (1.f / PI_F);
                float e1 = asinf(fminf(fmaxf(-ro20, -1.f), 1.f)) * (1.f / PI_F);
                float e2 = atan2f(ro21, ro22) * (1.f / PI_F);
                float vjx = xj[3], vjy = xj[4], vjz = xj[5];
                float rvx = r0 * vjx + r3 * vjy + r6 * vjz;
                float rvy = r1 * vjx + r4 * vjy + r7 * vjz;
                float rvz = r2 * vjx + r5 * vjy + r8 * vjz;
                se[h][0][e] = rrx;  se[h][1][e] = rry;   se[h][2][e] = rrz;
                se[h][3][e] = e0;   se[h][4][e] = e1;    se[h][5][e] = e2;
                se[h][6][e] = dist; se[h][7][e] = theta_e; se[h][8][e] = phi_e;
                se[h][9][e] = rvx;  se[h][10][e] = rvy;  se[h][11][e] = rvz;
            } else {
#pragma unroll
                for (int k = 0; k < 12; k++) se[h][k][e] = 0.f;
            }
        }
    }
    __syncthreads();

    // per-feature sums (48 threads per half: feature k, quarter p4)
    if (tt < 48 && active) {
        int k = tt >> 2, p4 = tt & 3;
        int lo = p4 * 32;
        int hi = (p4 + 1) * 32;
        if (hi > Em_pad) hi = Em_pad;
        float s = 0.f;
        for (int e = lo; e < hi; e++) s += se[h][k][e];
        sP[h][k][p4] = (lo < hi) ? s : 0.f;
    }

    // two channels per thread (within this half): ca=tt, cb=tt+64; HALVED w
    int ca = tt, cb = tt + 64;
    ull wa[12], wb[12];
#pragma unroll
    for (int k = 0; k < 12; k++) {
        float u = 0.5f * W1[k * H + ca];
        float v = 0.5f * W1[k * H + cb];
        wa[k] = pack2(u, u);
        wb[k] = pack2(v, v);
    }
    float cv0 = scv[h][0], cv1 = scv[h][1], cv2 = scv[h][2];
    float base_a = 0.5f * (b1[ca] + cv0 * W1[15 * H + ca] +
                           cv1 * W1[16 * H + ca] + cv2 * W1[17 * H + ca]);
    float base_b = 0.5f * (b1[cb] + cv0 * W1[15 * H + cb] +
                           cv1 * W1[16 * H + cb] + cv2 * W1[17 * H + cb]);
    ull bpa = pack2(base_a, base_a);
    ull bpb = pack2(base_b, base_b);

    __syncthreads();

    ull acc_a = 0ULL, acc_b = 0ULL;
    for (int je = 0; je < Em_pad; je += 4) {
        ull zxa = bpa, zya = bpa, zxb = bpb, zyb = bpb;
#pragma unroll
        for (int k = 0; k < 12; k++) {
            ulonglong2 p = *(const ulonglong2*)&se[h][k][je];
            zxa = fma2(p.x, wa[k], zxa);
            zya = fma2(p.y, wa[k], zya);
            zxb = fma2(p.x, wb[k], zxb);
            zyb = fma2(p.y, wb[k], zyb);
        }
        acc_a = tanh_acc(zxa, acc_a);
        acc_a = tanh_acc(zya, acc_a);
        acc_b = tanh_acc(zxb, acc_b);
        acc_b = tanh_acc(zyb, acc_b);
    }

    __syncthreads();  // sP visible

    if (active) {
        // analytic linear part: Sum_real z' = sumF . w' + Em * base'
        float lin_a = (float)Em * base_a;
        float lin_b = (float)Em * base_b;
#pragma unroll
        for (int k = 0; k < 12; k++) {
            float sF = sP[h][k][0] + sP[h][k][1] + sP[h][k][2] + sP[h][k][3];
            float wlo, whi, vlo, vhi;
            unpack2(wa[k], wlo, whi);
            unpack2(wb[k], vlo, vhi);
            lin_a += sF * wlo;
            lin_b += sF * vlo;
        }

        float a0, a1, b0v, b1v;
        unpack2(acc_a, a0, a1);
        unpack2(acc_b, b0v, b1v);
        float ts_a = a0 + a1;
        float ts_b = b0v + b1v;
        int npad = Em_pad - Em;
        if (npad) {  // padded edges contributed base'*tanh(base')
            ts_a -= (float)npad * (base_a * tanha(base_a));
            ts_b -= (float)npad * (base_b * tanha(base_b));
        }
        size_t bi = (size_t)b * N + i;
        g_hsum[bi * H + ca] = lin_a + ts_a;
        g_hsum[bi * H + cb] = lin_b + ts_b;
    }
}

// ---------------------------------------------------------------------------
// Kernel C: node MLP, 16 nodes per block, packed-f32x2 gemv.
// R and canonical velocity recomputed in-block (no g_R/g_cv dependency).
// ---------------------------------------------------------------------------
__device__ __forceinline__ void gemv16p(const float sh[16][H],
                                        const float* __restrict__ W, int t,
                                        float acc[16]) {
    ull a[16];
#pragma unroll
    for (int n = 0; n < 16; n++) a[n] = 0ULL;
    for (int m = 0; m < H; m += 4) {
        ull wp0 = pack2(W[(m + 0) * H + t], W[(m + 1) * H + t]);
        ull wp1 = pack2(W[(m + 2) * H + t], W[(m + 3) * H + t]);
#pragma unroll
        for (int n = 0; n < 16; n++) {
            ulonglong2 h = *(const ulonglong2*)&sh[n][m];
            a[n] = fma2(h.x, wp0, a[n]);
            a[n] = fma2(h.y, wp1, a[n]);
        }
    }
#pragma unroll
    for (int n = 0; n < 16; n++) {
        float x, y;
        unpack2(a[n], x, y);
        acc[n] = x + y;
    }
}

__global__ void node_mlp(const float* __restrict__ inputs,
                         const float* __restrict__ W2, const float* __restrict__ b2,
                         const float* __restrict__ Wr, const float* __restrict__ br,
                         const float* __restrict__ W3, const float* __restrict__ b3,
                         const float* __restrict__ W4, const float* __restrict__ b4,
                         const float* __restrict__ W5, const float* __restrict__ b5,
                         float* __restrict__ out, int BN, float inv_cnt) {
    int t = threadIdx.x;
    int n0 = blockIdx.x * 16;
    __shared__ __align__(16) float shA[16][H];
    __shared__ __align__(16) float shB[16][H];
    __shared__ float spred[16][6];
    __shared__ float sRm[16][9];
    __shared__ float scvm[16][3];

#pragma unroll
    for (int n = 0; n < 16; n++) {
        int node = n0 + n;
        shA[n][t] = (node < BN) ? g_hsum[(size_t)node * H + t] : 0.f;
    }
    // recompute R + cv for this block's nodes (replaces node_prep outputs)
    if (t < 16) {
        int node = n0 + t;
        if (node < BN) {
            float vx = inputs[(size_t)node * 6 + 3];
            float vy = inputs[(size_t)node * 6 + 4];
            float vz = inputs[(size_t)node * 6 + 5];
            float R[9];
            vel_to_R(vx, vy, vz, R);
#pragma unroll
            for (int k = 0; k < 9; k++) sRm[t][k] = R[k];
            scvm[t][0] = R[0] * vx + R[3] * vy + R[6] * vz;
            scvm[t][1] = R[1] * vx + R[4] * vy + R[7] * vz;
            scvm[t][2] = R[2] * vx + R[5] * vy + R[8] * vz;
        }
    }
    __syncthreads();

    float acc[16];
    gemv16p(shA, W2, t, acc);

    float wr3 = Wr[3 * H + t], wr4 = Wr[4 * H + t], wr5 = Wr[5 * H + t];
    float bb = b2[t] + br[t];
#pragma unroll
    for (int n = 0; n < 16; n++) {
        int node = n0 + n;
        float aug = 0.f;
        if (node < BN) {
            aug = acc[n] * inv_cnt + bb + scvm[n][0] * wr3 +
                  scvm[n][1] * wr4 + scvm[n][2] * wr5;
        }
        shB[n][t] = aug;
    }
    __syncthreads();

    gemv16p(shB, W3, t, acc);
    float bias3 = b3[t];
#pragma unroll
    for (int n = 0; n < 16; n++) shA[n][t] = fmaxf(acc[n] + bias3, 0.f);
    __syncthreads();

    gemv16p(shA, W4, t, acc);
    float bias4 = b4[t];
#pragma unroll
    for (int n = 0; n < 16; n++) shB[n][t] = fmaxf(acc[n] + bias4, 0.f);
    __syncthreads();

    // Epilogue: warp wn handles 4 nodes: lanes {0-5,8-13,16-21,24-29}
    int wn = t >> 5;
    int lane = t & 31;
    int l = lane & 7;
    int n = 4 * wn + (lane >> 3);
    int node = n0 + n;
    if (l < 6 && node < BN) {
        float a = b5[l];
        for (int m = 0; m < H; m++) a += shB[n][m] * W5[m * 6 + l];
        spred[n][l] = a;
    }
    __syncwarp();
    if (l < 6 && node < BN) {
        int r = l % 3;
        int s = (l / 3) * 3;
        float gl = sRm[n][r * 3 + 0] * spred[n][s + 0] +
                   sRm[n][r * 3 + 1] * spred[n][s + 1] +
                   sRm[n][r * 3 + 2] * spred[n][s + 2];
        out[(size_t)node * 6 + l] = inputs[(size_t)node * 6 + l] + gl;
    }
}

// ---------------------------------------------------------------------------
extern "C" void kernel_launch(void* const* d_in, const int* in_sizes, int n_in,
                              void* d_out, int out_size) {
    const float* inputs = (const float*)d_in[0];
    const float* W1 = (const float*)d_in[1];
    const float* b1 = (const float*)d_in[2];
    const float* W2 = (const float*)d_in[3];
    const float* b2 = (const float*)d_in[4];
    const float* Wr = (const float*)d_in[5];
    const float* br = (const float*)d_in[6];
    const float* W3 = (const float*)d_in[7];
    const float* b3 = (const float*)d_in[8];
    const float* W4 = (const float*)d_in[9];
    const float* b4 = (const float*)d_in[10];
    const float* W5 = (const float*)d_in[11];
    const float* b5 = (const float*)d_in[12];

    int E = in_sizes[14];  // recv_edges count = N*(N-1)
    int N = (int)((1.0 + sqrt(1.0 + 4.0 * (double)E)) / 2.0 + 0.5);
    int BN = in_sizes[0] / 6;
    if (N < 2 || N > 128 || BN > MAXBN) return;
    int B = BN / N;
    int pairsPerRow = (N + 1) / 2;
    float inv_cnt = 1.0f / (float)(N - 1);

    edge_kernel<<<B * pairsPerRow, 128>>>(inputs, W1, b1, N);
    node_mlp<<<(BN + 15) / 16, H>>>(inputs, W2, b2, Wr, br, W3, b3, W4, b4,
                                    W5, b5, (float*)d_out, BN, inv_cnt);
}